// round 6
// baseline (speedup 1.0000x reference)
#include <cuda_runtime.h>
#include <cuda_bf16.h>
#include <cstdint>

// Problem constants
#define BATCH  4
#define SEQ    4096
#define M_TOK  (BATCH * SEQ)   // 16384 tokens
#define EDIM   1024
#define HEADS  16
#define DH     64
#define NTOT   3072            // packed N = q|k|v

// bf16 has 7 stored mantissa bits -> residual |x - bf16(x)| <= |x| * 2^-8.
// Level ratio between hi and lo int8 grids must therefore be 256 (NOT 512).
#define RATIO  256.0f
#define INV_RATIO (1.0f / 256.0f)

typedef unsigned long long u64;
typedef unsigned int       u32;

// ---------------------------------------------------------------------------
// Device scratch (alloc-free per harness rules)
// ---------------------------------------------------------------------------
__device__ __nv_bfloat16 g_abf[(size_t)M_TOK * EDIM];   // Xh = bf16(x)
__device__ __nv_bfloat16 g_bbf[(size_t)NTOT * EDIM];    // Wh = bf16(W)
__device__ signed char   g_a8[(size_t)M_TOK * 2048];    // [Ah | Al]
__device__ signed char   g_b8[(size_t)NTOT * 2048];     // [Bl | Bh]
__device__ float         g_dx[M_TOK];                   // dxh per token row
__device__ float         g_dw[NTOT];                    // dwh per output channel
__device__ float         g_bias[NTOT];
__device__ float         g_qkv[(size_t)M_TOK * NTOT];   // q | k | v per row

// ---------------------------------------------------------------------------
// PTX helpers (compute_103-legal: cp.async / ldmatrix / mma.sync)
// ---------------------------------------------------------------------------
__device__ __forceinline__ u32 s2u(const void* p) {
    u32 a;
    asm("{ .reg .u64 t; cvta.to.shared.u64 t, %1; cvt.u32.u64 %0, t; }"
        : "=r"(a) : "l"(p));
    return a;
}
__device__ __forceinline__ void cpa16(u32 dst, const void* src) {
    asm volatile("cp.async.cg.shared.global [%0], [%1], 16;"
                 :: "r"(dst), "l"(src) : "memory");
}
#define CPA_COMMIT() asm volatile("cp.async.commit_group;" ::: "memory")
#define CPA_WAIT2()  asm volatile("cp.async.wait_group 2;" ::: "memory")

__device__ __forceinline__ void ldsm4(u32* r, u32 addr) {
    asm volatile("ldmatrix.sync.aligned.m8n8.x4.shared.b16 {%0,%1,%2,%3}, [%4];"
                 : "=r"(r[0]), "=r"(r[1]), "=r"(r[2]), "=r"(r[3]) : "r"(addr));
}
__device__ __forceinline__ void mma_bf16(float* d, const u32* a, const u32* b) {
    asm volatile(
        "mma.sync.aligned.m16n8k16.row.col.f32.bf16.bf16.f32 "
        "{%0,%1,%2,%3}, {%4,%5,%6,%7}, {%8,%9}, {%0,%1,%2,%3};"
        : "+f"(d[0]), "+f"(d[1]), "+f"(d[2]), "+f"(d[3])
        : "r"(a[0]), "r"(a[1]), "r"(a[2]), "r"(a[3]), "r"(b[0]), "r"(b[1]));
}
__device__ __forceinline__ void mma_s8(int* d, const u32* a, const u32* b) {
    asm volatile(
        "mma.sync.aligned.m16n8k32.row.col.s32.s8.s8.s32 "
        "{%0,%1,%2,%3}, {%4,%5,%6,%7}, {%8,%9}, {%0,%1,%2,%3};"
        : "+r"(d[0]), "+r"(d[1]), "+r"(d[2]), "+r"(d[3])
        : "r"(a[0]), "r"(a[1]), "r"(a[2]), "r"(a[3]), "r"(b[0]), "r"(b[1]));
}

// clamped int8 quantizer
__device__ __forceinline__ signed char q8(float v) {
    return (signed char)__float2int_rn(fminf(fmaxf(v, -127.0f), 127.0f));
}

// ---------------------------------------------------------------------------
// Pack kernels: bf16 hi part + two-level int8 residual encoding.
// One warp per row. Level ratio 256 => lo values provably fit int8.
// Both cross terms share the exact s32 accumulator scale dx*dw/256.
// ---------------------------------------------------------------------------
__device__ __forceinline__ float warp_max(float v) {
    #pragma unroll
    for (int o = 16; o > 0; o >>= 1)
        v = fmaxf(v, __shfl_xor_sync(0xFFFFFFFFu, v, o));
    return v;
}

// lo_slot0: if true, lo level goes to byte offset [0,1024) and hi to [1024,2048)
// (used for B so that [Ah|Al] x [Bl|Bh] = Ah*Bl + Al*Bh).
__device__ __forceinline__ void pack_row(const float* __restrict__ src,
                                         __nv_bfloat16* __restrict__ hw,
                                         signed char* __restrict__ i8,
                                         float* __restrict__ dvec,
                                         int row, int lane, bool lo_slot0)
{
    const float4* s4 = (const float4*)(src) + row * 256 + lane;
    float4 v[8];
    float mx = 0.f;
    #pragma unroll
    for (int j = 0; j < 8; j++) {
        v[j] = s4[j * 32];
        mx = fmaxf(mx, fmaxf(fmaxf(fabsf(v[j].x), fabsf(v[j].y)),
                             fmaxf(fabsf(v[j].z), fabsf(v[j].w))));
    }
    mx = warp_max(mx);
    const float inv_h = 127.0f / mx;
    const float inv_l = inv_h * RATIO;
    if (lane == 0) dvec[row] = mx / 127.0f;

    const int off_h = lo_slot0 ? 1024 : 0;
    const int off_l = lo_slot0 ? 0 : 1024;

    __nv_bfloat16* hrow = hw + (size_t)row * EDIM;
    signed char* irow   = i8 + (size_t)row * 2048;
    #pragma unroll
    for (int j = 0; j < 8; j++) {
        const int e = j * 128 + lane * 4;
        float4 vv = v[j];
        __nv_bfloat16 h0 = __float2bfloat16(vv.x);
        __nv_bfloat16 h1 = __float2bfloat16(vv.y);
        __nv_bfloat16 h2 = __float2bfloat16(vv.z);
        __nv_bfloat16 h3 = __float2bfloat16(vv.w);
        *(__nv_bfloat162*)(hrow + e)     = __halves2bfloat162(h0, h1);
        *(__nv_bfloat162*)(hrow + e + 2) = __halves2bfloat162(h2, h3);
        char4 qh = make_char4(q8(vv.x * inv_h), q8(vv.y * inv_h),
                              q8(vv.z * inv_h), q8(vv.w * inv_h));
        char4 ql = make_char4(
            q8((vv.x - __bfloat162float(h0)) * inv_l),
            q8((vv.y - __bfloat162float(h1)) * inv_l),
            q8((vv.z - __bfloat162float(h2)) * inv_l),
            q8((vv.w - __bfloat162float(h3)) * inv_l));
        *(char4*)(irow + off_h + e) = qh;
        *(char4*)(irow + off_l + e) = ql;
    }
}

__global__ void pack_a(const float* __restrict__ x) {
    const int row  = blockIdx.x * 8 + (threadIdx.x >> 5);
    const int lane = threadIdx.x & 31;
    pack_row(x, g_abf, g_a8, g_dx, row, lane, false);   // [Ah | Al]
}

__global__ void pack_b(const float* __restrict__ Wq,
                       const float* __restrict__ Wk,
                       const float* __restrict__ Wv) {
    const int row  = blockIdx.x * 8 + (threadIdx.x >> 5);
    const int lane = threadIdx.x & 31;
    const int z = row >> 10;
    const float* src = (z == 0 ? Wq : z == 1 ? Wk : Wv) - (size_t)(z << 10) * EDIM;
    pack_row(src, g_bbf, g_b8, g_dw, row, lane, true);  // [Bl | Bh]
}

__global__ void pack_bias(const float* __restrict__ bq,
                          const float* __restrict__ bk,
                          const float* __restrict__ bv) {
    int i = blockIdx.x * blockDim.x + threadIdx.x;
    if (i < NTOT) {
        const int z = i >> 10;
        g_bias[i] = (z == 0 ? bq : z == 1 ? bk : bv)[i & 1023];
    }
}

// ---------------------------------------------------------------------------
// Two-phase GEMM: phase 1 int8 cross terms (16 iters of k128-int8),
// phase 2 bf16 main term (16 iters of k64-bf16). 128x256 CTA tile, 256 thr,
// 8 warps of 64x64, 4-stage cp.async pipeline shared across the phases.
// ---------------------------------------------------------------------------
#define GBM 128
#define GBN 256
#define NSTG 4
#define I8_IT 16
#define TOT_IT 32
#define A_STG 16384               // 128 rows * 128B
#define B_STG 32768               // 256 rows * 128B
#define STG_BYTES (A_STG + B_STG) // 49152
#define SMEM_GEMM (NSTG * STG_BYTES + 128)

__device__ __forceinline__ u32 swz(int row, int c) {
    return (u32)(row * 128 + ((c ^ (row & 7)) << 4));
}

__device__ __forceinline__ void load_stage(u32 smb, int slot, int it,
                                           int row0, int col0, int tid) {
    const u32 aB = smb + slot * STG_BYTES;
    const u32 bB = aB + A_STG;
    if (it < I8_IT) {
        #pragma unroll
        for (int j = 0; j < 4; j++) {
            const int ci = tid + j * 256;
            const int r = ci >> 3, c = ci & 7;
            cpa16(aB + swz(r, c),
                  g_a8 + (size_t)(row0 + r) * 2048 + it * 128 + c * 16);
        }
        #pragma unroll
        for (int j = 0; j < 8; j++) {
            const int ci = tid + j * 256;
            const int r = ci >> 3, c = ci & 7;
            cpa16(bB + swz(r, c),
                  g_b8 + (size_t)(col0 + r) * 2048 + it * 128 + c * 16);
        }
    } else {
        const int it2 = it - I8_IT;
        #pragma unroll
        for (int j = 0; j < 4; j++) {
            const int ci = tid + j * 256;
            const int r = ci >> 3, c = ci & 7;
            cpa16(aB + swz(r, c),
                  g_abf + (size_t)(row0 + r) * EDIM + it2 * 64 + c * 8);
        }
        #pragma unroll
        for (int j = 0; j < 8; j++) {
            const int ci = tid + j * 256;
            const int r = ci >> 3, c = ci & 7;
            cpa16(bB + swz(r, c),
                  g_bbf + (size_t)(col0 + r) * EDIM + it2 * 64 + c * 8);
        }
    }
}

__global__ void __launch_bounds__(256, 1)
qkv_mma_gemm()
{
    extern __shared__ char smraw[];
    const u32 smb = (s2u(smraw) + 127u) & ~127u;

    const int tid  = threadIdx.x;
    const int wid  = tid >> 5;
    const int lane = tid & 31;
    const int wm   = wid & 1;          // 0..1 -> 64 rows
    const int wn   = wid >> 1;         // 0..3 -> 64 cols
    const int row0 = blockIdx.y * GBM;
    const int col0 = blockIdx.x * GBN;

    // prologue: stages 0,1,2 (int8 phase)
    load_stage(smb, 0, 0, row0, col0, tid); CPA_COMMIT();
    load_stage(smb, 1, 1, row0, col0, tid); CPA_COMMIT();
    load_stage(smb, 2, 2, row0, col0, tid); CPA_COMMIT();

    // ---- phase 1: int8 cross terms ----
    int iacc[4][8][4];
    #pragma unroll
    for (int i = 0; i < 4; i++)
        #pragma unroll
        for (int j = 0; j < 8; j++)
            #pragma unroll
            for (int k = 0; k < 4; k++) iacc[i][j][k] = 0;

    for (int kt = 0; kt < I8_IT; kt++) {
        CPA_WAIT2();
        __syncthreads();
        load_stage(smb, (kt + 3) & 3, kt + 3, row0, col0, tid);
        CPA_COMMIT();

        const u32 aB = smb + (kt & 3) * STG_BYTES;
        const u32 bB = aB + A_STG;
        #pragma unroll
        for (int kk = 0; kk < 4; kk++) {       // each kk = k32 int8
            u32 ra[4][4];
            #pragma unroll
            for (int mi = 0; mi < 4; mi++) {
                const int r = wm * 64 + mi * 16 + (lane & 15);
                const int c = kk * 2 + (lane >> 4);
                ldsm4(ra[mi], aB + swz(r, c));
            }
            u32 rb[4][4];
            #pragma unroll
            for (int ni = 0; ni < 4; ni++) {
                const int r = wn * 64 + ni * 16 + (lane & 7) + ((lane >> 4) << 3);
                const int c = kk * 2 + ((lane >> 3) & 1);
                ldsm4(rb[ni], bB + swz(r, c));
            }
            #pragma unroll
            for (int mi = 0; mi < 4; mi++)
                #pragma unroll
                for (int n8 = 0; n8 < 8; n8++)
                    mma_s8(iacc[mi][n8], ra[mi], &rb[n8 >> 1][(n8 & 1) * 2]);
        }
    }

    // ---- convert: facc = iacc * dxh[m] * dwh[n] / 256 ----
    const int rbase = row0 + wm * 64;
    const int cbase = col0 + wn * 64;
    float dxr[4][2], dwc[8][2];
    #pragma unroll
    for (int mi = 0; mi < 4; mi++) {
        const int r = rbase + mi * 16 + (lane >> 2);
        dxr[mi][0] = g_dx[r] * INV_RATIO;
        dxr[mi][1] = g_dx[r + 8] * INV_RATIO;
    }
    #pragma unroll
    for (int n8 = 0; n8 < 8; n8++) {
        const int c = cbase + n8 * 8 + (lane & 3) * 2;
        dwc[n8][0] = g_dw[c];
        dwc[n8][1] = g_dw[c + 1];
    }

    float facc[4][8][4];
    #pragma unroll
    for (int mi = 0; mi < 4; mi++)
        #pragma unroll
        for (int n8 = 0; n8 < 8; n8++) {
            facc[mi][n8][0] = (float)iacc[mi][n8][0] * dxr[mi][0] * dwc[n8][0];
            facc[mi][n8][1] = (float)iacc[mi][n8][1] * dxr[mi][0] * dwc[n8][1];
            facc[mi][n8][2] = (float)iacc[mi][n8][2] * dxr[mi][1] * dwc[n8][0];
            facc[mi][n8][3] = (float)iacc[mi][n8][3] * dxr[mi][1] * dwc[n8][1];
        }

    // ---- phase 2: bf16 main term ----
    for (int kt = I8_IT; kt < TOT_IT; kt++) {
        CPA_WAIT2();
        __syncthreads();
        if (kt + 3 < TOT_IT)
            load_stage(smb, (kt + 3) & 3, kt + 3, row0, col0, tid);
        CPA_COMMIT();

        const u32 aB = smb + (kt & 3) * STG_BYTES;
        const u32 bB = aB + A_STG;
        #pragma unroll
        for (int kk = 0; kk < 4; kk++) {       // each kk = k16 bf16
            u32 ra[4][4];
            #pragma unroll
            for (int mi = 0; mi < 4; mi++) {
                const int r = wm * 64 + mi * 16 + (lane & 15);
                const int c = kk * 2 + (lane >> 4);
                ldsm4(ra[mi], aB + swz(r, c));
            }
            u32 rb[4][4];
            #pragma unroll
            for (int ni = 0; ni < 4; ni++) {
                const int r = wn * 64 + ni * 16 + (lane & 7) + ((lane >> 4) << 3);
                const int c = kk * 2 + ((lane >> 3) & 1);
                ldsm4(rb[ni], bB + swz(r, c));
            }
            #pragma unroll
            for (int mi = 0; mi < 4; mi++)
                #pragma unroll
                for (int n8 = 0; n8 < 8; n8++)
                    mma_bf16(facc[mi][n8], ra[mi], &rb[n8 >> 1][(n8 & 1) * 2]);
        }
    }

    // ---- epilogue: add bias, write g_qkv ----
    #pragma unroll
    for (int mi = 0; mi < 4; mi++) {
        const int r = rbase + mi * 16 + (lane >> 2);
        #pragma unroll
        for (int n8 = 0; n8 < 8; n8++) {
            const int c = cbase + n8 * 8 + (lane & 3) * 2;
            const float b0 = g_bias[c], b1 = g_bias[c + 1];
            float2 v0 = make_float2(facc[mi][n8][0] + b0, facc[mi][n8][1] + b1);
            float2 v1 = make_float2(facc[mi][n8][2] + b0, facc[mi][n8][3] + b1);
            *(float2*)&g_qkv[(size_t)r * NTOT + c]       = v0;
            *(float2*)&g_qkv[(size_t)(r + 8) * NTOT + c] = v1;
        }
    }
}

// ---------------------------------------------------------------------------
// Per-token head-head attention (mask-before-softmax semantics).
// ---------------------------------------------------------------------------
__global__ __launch_bounds__(128)
void attn_kernel(const float* __restrict__ mask, float* __restrict__ out)
{
    __shared__ float ks[4 * HEADS * DH];
    __shared__ float vs[4 * HEADS * DH];
    __shared__ float ms[HEADS * HEADS];

    const int tid = threadIdx.x;
    const size_t tok0 = (size_t)blockIdx.x * 4;

    for (int i = tid; i < HEADS * HEADS; i += 128) ms[i] = mask[i];

    float4* ks4 = (float4*)ks;
    float4* vs4 = (float4*)vs;
    #pragma unroll
    for (int tt = 0; tt < 4; tt++) {
        const float4* kg = (const float4*)(g_qkv + (tok0 + tt) * NTOT + EDIM);
        const float4* vg = (const float4*)(g_qkv + (tok0 + tt) * NTOT + 2 * EDIM);
        #pragma unroll
        for (int j = 0; j < 2; j++) {
            const int idx = tid + j * 128;
            ks4[tt * 256 + idx] = kg[idx];
            vs4[tt * 256 + idx] = vg[idx];
        }
    }
    __syncthreads();

    const int t    = tid >> 5;
    const int lane = tid & 31;
    const int h    = lane & 15;
    const int half = lane >> 4;

    float4 qv[8];
    const float4* qp = (const float4*)(g_qkv + (tok0 + t) * NTOT + h * DH + half * 32);
    #pragma unroll
    for (int i = 0; i < 8; i++) qv[i] = qp[i];

    float s[16];
    #pragma unroll
    for (int g = 0; g < 16; g++) {
        const float4* kr = (const float4*)(ks + (t * HEADS + g) * DH + half * 32);
        float ax = 0.f, ay = 0.f, az = 0.f, aw = 0.f;
        #pragma unroll
        for (int i = 0; i < 8; i++) {
            float4 kv = kr[i];
            ax += qv[i].x * kv.x; ay += qv[i].y * kv.y;
            az += qv[i].z * kv.z; aw += qv[i].w * kv.w;
        }
        float p = (ax + ay) + (az + aw);
        p += __shfl_xor_sync(0xFFFFFFFFu, p, 16);
        s[g] = p * ms[h * HEADS + g];
    }

    float m = s[0];
    #pragma unroll
    for (int g = 1; g < 16; g++) m = fmaxf(m, s[g]);
    float denom = 0.f;
    #pragma unroll
    for (int g = 0; g < 16; g++) { s[g] = expf(s[g] - m); denom += s[g]; }
    const float inv = 1.f / denom;

    float4 o[8];
    #pragma unroll
    for (int i = 0; i < 8; i++) o[i] = make_float4(0.f, 0.f, 0.f, 0.f);
    #pragma unroll
    for (int g = 0; g < 16; g++) {
        const float p = s[g] * inv;
        const float4* vr = (const float4*)(vs + (t * HEADS + g) * DH + half * 32);
        #pragma unroll
        for (int i = 0; i < 8; i++) {
            float4 vv = vr[i];
            o[i].x += p * vv.x; o[i].y += p * vv.y;
            o[i].z += p * vv.z; o[i].w += p * vv.w;
        }
    }

    float4* op = (float4*)(out + (tok0 + t) * EDIM + h * DH + half * 32);
    #pragma unroll
    for (int i = 0; i < 8; i++) op[i] = o[i];
}

// ---------------------------------------------------------------------------
// Launch. Inputs: x, sparsity_pattern, Wq, bq, Wk, bk, Wv, bv
// ---------------------------------------------------------------------------
extern "C" void kernel_launch(void* const* d_in, const int* in_sizes, int n_in,
                              void* d_out, int out_size)
{
    (void)in_sizes; (void)n_in; (void)out_size;
    const float* x  = (const float*)d_in[0];
    const float* sp = (const float*)d_in[1];
    const float* Wq = (const float*)d_in[2];
    const float* bq = (const float*)d_in[3];
    const float* Wk = (const float*)d_in[4];
    const float* bk = (const float*)d_in[5];
    const float* Wv = (const float*)d_in[6];
    const float* bv = (const float*)d_in[7];
    float* out = (float*)d_out;

    pack_a<<<M_TOK / 8, 256>>>(x);
    pack_b<<<NTOT / 8, 256>>>(Wq, Wk, Wv);
    pack_bias<<<12, 256>>>(bq, bk, bv);

    cudaFuncSetAttribute(qkv_mma_gemm,
                         cudaFuncAttributeMaxDynamicSharedMemorySize, SMEM_GEMM);
    dim3 grid(NTOT / GBN, M_TOK / GBM);    // (12, 128)
    qkv_mma_gemm<<<grid, 256, SMEM_GEMM>>>();

    attn_kernel<<<M_TOK / 4, 128>>>(sp, out);
}

// round 7
// speedup vs baseline: 2.3041x; 2.3041x over previous
#include <cuda_runtime.h>
#include <cuda_bf16.h>
#include <cstdint>

// Problem constants
#define BATCH  4
#define SEQ    4096
#define M_TOK  (BATCH * SEQ)   // 16384 tokens
#define EDIM   1024
#define HEADS  16
#define DH     64

#define KTOT   3072            // packed K = 3*EDIM (hi|hi|lo)
#define NTOT   3072            // packed N = q|k|v

typedef unsigned long long u64;
typedef unsigned int       u32;

// ---------------------------------------------------------------------------
// Device scratch (alloc-free per harness rules)
// ---------------------------------------------------------------------------
__device__ __nv_bfloat16 g_ap[(size_t)M_TOK * KTOT];   // [Xhi | Xhi | Xlo]
__device__ __nv_bfloat16 g_bp[(size_t)NTOT * KTOT];    // rows: [Whi | Wlo | Whi]
__device__ float         g_bias[NTOT];
__device__ float         g_qkv[(size_t)M_TOK * NTOT];  // q | k | v per row

// ---------------------------------------------------------------------------
// PTX helpers (compute_103-legal: cp.async / ldmatrix / mma.sync)
// ---------------------------------------------------------------------------
__device__ __forceinline__ u32 s2u(const void* p) {
    u32 a;
    asm("{ .reg .u64 t; cvta.to.shared.u64 t, %1; cvt.u32.u64 %0, t; }"
        : "=r"(a) : "l"(p));
    return a;
}
__device__ __forceinline__ void cpa16(u32 dst, const void* src) {
    asm volatile("cp.async.cg.shared.global [%0], [%1], 16;"
                 :: "r"(dst), "l"(src) : "memory");
}
#define CPA_COMMIT() asm volatile("cp.async.commit_group;" ::: "memory")
#define CPA_WAIT1()  asm volatile("cp.async.wait_group 1;" ::: "memory")

__device__ __forceinline__ void ldsm4(u32* r, u32 addr) {
    asm volatile("ldmatrix.sync.aligned.m8n8.x4.shared.b16 {%0,%1,%2,%3}, [%4];"
                 : "=r"(r[0]), "=r"(r[1]), "=r"(r[2]), "=r"(r[3]) : "r"(addr));
}
__device__ __forceinline__ void mma_bf16(float* d, const u32* a, const u32* b) {
    asm volatile(
        "mma.sync.aligned.m16n8k16.row.col.f32.bf16.bf16.f32 "
        "{%0,%1,%2,%3}, {%4,%5,%6,%7}, {%8,%9}, {%0,%1,%2,%3};"
        : "+f"(d[0]), "+f"(d[1]), "+f"(d[2]), "+f"(d[3])
        : "r"(a[0]), "r"(a[1]), "r"(a[2]), "r"(a[3]), "r"(b[0]), "r"(b[1]));
}

// ---------------------------------------------------------------------------
// Pack kernels: hi/lo bf16 split into the K-concat layout (proven in R4)
// ---------------------------------------------------------------------------
__device__ __forceinline__ void split4(float4 v, __nv_bfloat162& h01, __nv_bfloat162& h23,
                                       __nv_bfloat162& l01, __nv_bfloat162& l23) {
    __nv_bfloat16 h0 = __float2bfloat16(v.x);
    __nv_bfloat16 h1 = __float2bfloat16(v.y);
    __nv_bfloat16 h2 = __float2bfloat16(v.z);
    __nv_bfloat16 h3 = __float2bfloat16(v.w);
    h01 = __halves2bfloat162(h0, h1);
    h23 = __halves2bfloat162(h2, h3);
    l01 = __halves2bfloat162(__float2bfloat16(v.x - __bfloat162float(h0)),
                             __float2bfloat16(v.y - __bfloat162float(h1)));
    l23 = __halves2bfloat162(__float2bfloat16(v.z - __bfloat162float(h2)),
                             __float2bfloat16(v.w - __bfloat162float(h3)));
}

__global__ void pack_x(const float4* __restrict__ x) {
    int i = blockIdx.x * blockDim.x + threadIdx.x;
    const int n4 = M_TOK * EDIM / 4;
    const int stride = gridDim.x * blockDim.x;
    __nv_bfloat162* out = (__nv_bfloat162*)g_ap;
    for (; i < n4; i += stride) {
        float4 v = x[i];
        __nv_bfloat162 h01, h23, l01, l23;
        split4(v, h01, h23, l01, l23);
        const int e0  = i * 4;
        const int row = e0 >> 10;
        const int col = e0 & 1023;
        const size_t base = ((size_t)row * KTOT + col) >> 1;
        out[base]        = h01;  out[base + 1]    = h23;   // hi
        out[base + 512]  = h01;  out[base + 513]  = h23;   // hi
        out[base + 1024] = l01;  out[base + 1025] = l23;   // lo
    }
}

__global__ void pack_w(const float4* __restrict__ Wq,
                       const float4* __restrict__ Wk,
                       const float4* __restrict__ Wv) {
    int i = blockIdx.x * blockDim.x + threadIdx.x;
    const int per = EDIM * EDIM / 4;
    const int n4 = 3 * per;
    const int stride = gridDim.x * blockDim.x;
    __nv_bfloat162* out = (__nv_bfloat162*)g_bp;
    for (; i < n4; i += stride) {
        const int z = i / per;
        const int r = i - z * per;
        float4 v = (z == 0 ? Wq : z == 1 ? Wk : Wv)[r];
        __nv_bfloat162 h01, h23, l01, l23;
        split4(v, h01, h23, l01, l23);
        const int e0  = r * 4;
        const int row = e0 >> 10;
        const int col = e0 & 1023;
        const size_t base = ((size_t)(z * EDIM + row) * KTOT + col) >> 1;
        out[base]        = h01;  out[base + 1]    = h23;   // hi
        out[base + 512]  = l01;  out[base + 513]  = l23;   // lo
        out[base + 1024] = h01;  out[base + 1025] = h23;   // hi
    }
}

__global__ void pack_bias(const float* __restrict__ bq,
                          const float* __restrict__ bk,
                          const float* __restrict__ bv) {
    int i = blockIdx.x * blockDim.x + threadIdx.x;
    if (i < NTOT) {
        const int z = i >> 10;
        g_bias[i] = (z == 0 ? bq : z == 1 ? bk : bv)[i & 1023];
    }
}

// ---------------------------------------------------------------------------
// bf16 mma.sync GEMM: C[m,n] = sum_k Apack[m,k]*Bpack[n,k] + bias[n]
// CTA tile 128x128, 256 threads (8 warps, 2Mx4N, 64x32 warp tiles),
// 3-stage cp.async pipeline, __launch_bounds__(256,2) => 2 CTAs/SM
// (16 warps/SM = 4 per SMSP for latency hiding).
// ---------------------------------------------------------------------------
#define GBM 128
#define GBN 128
#define GBK 64
#define NSTG 3
#define KIT (KTOT / GBK)          // 48
#define A_STG 16384               // 128 rows * 128B
#define B_STG 16384               // 128 rows * 128B
#define STG_BYTES (A_STG + B_STG) // 32768
#define SMEM_GEMM (NSTG * STG_BYTES + 128)

// swizzled smem byte offset for (row, 16B-chunk c) in a 128B-row tile
__device__ __forceinline__ u32 swz(int row, int c) {
    return (u32)(row * 128 + ((c ^ (row & 7)) << 4));
}

__device__ __forceinline__ void load_stage(u32 smb, int slot, int kt,
                                           int row0, int col0, int tid) {
    const u32 aB = smb + slot * STG_BYTES;
    const u32 bB = aB + A_STG;
    // A: 1024 chunks (128 rows x 8), 4 per thread
    #pragma unroll
    for (int j = 0; j < 4; j++) {
        const int ci = tid + j * 256;
        const int r = ci >> 3, c = ci & 7;
        cpa16(aB + swz(r, c),
              g_ap + (size_t)(row0 + r) * KTOT + kt * GBK + c * 8);
    }
    // B: 1024 chunks (128 rows x 8), 4 per thread
    #pragma unroll
    for (int j = 0; j < 4; j++) {
        const int ci = tid + j * 256;
        const int r = ci >> 3, c = ci & 7;
        cpa16(bB + swz(r, c),
              g_bp + (size_t)(col0 + r) * KTOT + kt * GBK + c * 8);
    }
}

__global__ void __launch_bounds__(256, 2)
qkv_mma_gemm()
{
    extern __shared__ char smraw[];
    const u32 smb = (s2u(smraw) + 127u) & ~127u;

    const int tid  = threadIdx.x;
    const int wid  = tid >> 5;
    const int lane = tid & 31;
    const int wm   = wid & 1;          // 0..1 -> 64 rows
    const int wn   = wid >> 1;         // 0..3 -> 32 cols
    const int row0 = blockIdx.y * GBM;
    const int col0 = blockIdx.x * GBN;

    float acc[4][4][4];                // 4 mi (16 rows) x 4 n8 (8 cols) x 4
    #pragma unroll
    for (int i = 0; i < 4; i++)
        #pragma unroll
        for (int j = 0; j < 4; j++)
            #pragma unroll
            for (int k = 0; k < 4; k++) acc[i][j][k] = 0.f;

    // prologue: stages 0,1
    load_stage(smb, 0, 0, row0, col0, tid); CPA_COMMIT();
    load_stage(smb, 1, 1, row0, col0, tid); CPA_COMMIT();

    int slot = 0;
    for (int kt = 0; kt < KIT; kt++) {
        CPA_WAIT1();
        __syncthreads();

        // issue next stage immediately (that slot was last read pre-barrier)
        if (kt + 2 < KIT) {
            int ns = slot + 2; if (ns >= NSTG) ns -= NSTG;
            load_stage(smb, ns, kt + 2, row0, col0, tid);
        }
        CPA_COMMIT();

        const u32 aB = smb + slot * STG_BYTES;
        const u32 bB = aB + A_STG;

        #pragma unroll
        for (int kk = 0; kk < 4; kk++) {
            u32 ra[4][4];
            #pragma unroll
            for (int mi = 0; mi < 4; mi++) {
                const int r = wm * 64 + mi * 16 + (lane & 15);
                const int c = kk * 2 + (lane >> 4);
                ldsm4(ra[mi], aB + swz(r, c));
            }
            u32 rb[2][4];
            #pragma unroll
            for (int ni = 0; ni < 2; ni++) {
                const int r = wn * 32 + ni * 16 + (lane & 7) + ((lane >> 4) << 3);
                const int c = kk * 2 + ((lane >> 3) & 1);
                ldsm4(rb[ni], bB + swz(r, c));
            }
            #pragma unroll
            for (int mi = 0; mi < 4; mi++)
                #pragma unroll
                for (int n8 = 0; n8 < 4; n8++)
                    mma_bf16(acc[mi][n8], ra[mi], &rb[n8 >> 1][(n8 & 1) * 2]);
        }

        if (++slot == NSTG) slot = 0;
    }

    // epilogue: add bias, write g_qkv
    const int rbase = row0 + wm * 64;
    const int cbase = col0 + wn * 32;
    #pragma unroll
    for (int mi = 0; mi < 4; mi++) {
        const int r = rbase + mi * 16 + (lane >> 2);
        #pragma unroll
        for (int n8 = 0; n8 < 4; n8++) {
            const int c = cbase + n8 * 8 + (lane & 3) * 2;
            const float b0 = g_bias[c], b1 = g_bias[c + 1];
            float2 v0 = make_float2(acc[mi][n8][0] + b0, acc[mi][n8][1] + b1);
            float2 v1 = make_float2(acc[mi][n8][2] + b0, acc[mi][n8][3] + b1);
            *(float2*)&g_qkv[(size_t)r * NTOT + c]       = v0;
            *(float2*)&g_qkv[(size_t)(r + 8) * NTOT + c] = v1;
        }
    }
}

// ---------------------------------------------------------------------------
// Per-token head-head attention (proven in R4; mask-before-softmax).
// 128 threads / 4 tokens per block; 32 threads per token = (head, D-half).
// ---------------------------------------------------------------------------
__global__ __launch_bounds__(128)
void attn_kernel(const float* __restrict__ mask, float* __restrict__ out)
{
    __shared__ float ks[4 * HEADS * DH];
    __shared__ float vs[4 * HEADS * DH];
    __shared__ float ms[HEADS * HEADS];

    const int tid = threadIdx.x;
    const size_t tok0 = (size_t)blockIdx.x * 4;

    for (int i = tid; i < HEADS * HEADS; i += 128) ms[i] = mask[i];

    float4* ks4 = (float4*)ks;
    float4* vs4 = (float4*)vs;
    #pragma unroll
    for (int tt = 0; tt < 4; tt++) {
        const float4* kg = (const float4*)(g_qkv + (tok0 + tt) * NTOT + EDIM);
        const float4* vg = (const float4*)(g_qkv + (tok0 + tt) * NTOT + 2 * EDIM);
        #pragma unroll
        for (int j = 0; j < 2; j++) {
            const int idx = tid + j * 128;
            ks4[tt * 256 + idx] = kg[idx];
            vs4[tt * 256 + idx] = vg[idx];
        }
    }
    __syncthreads();

    const int t    = tid >> 5;
    const int lane = tid & 31;
    const int h    = lane & 15;
    const int half = lane >> 4;

    float4 qv[8];
    const float4* qp = (const float4*)(g_qkv + (tok0 + t) * NTOT + h * DH + half * 32);
    #pragma unroll
    for (int i = 0; i < 8; i++) qv[i] = qp[i];

    float s[16];
    #pragma unroll
    for (int g = 0; g < 16; g++) {
        const float4* kr = (const float4*)(ks + (t * HEADS + g) * DH + half * 32);
        float ax = 0.f, ay = 0.f, az = 0.f, aw = 0.f;
        #pragma unroll
        for (int i = 0; i < 8; i++) {
            float4 kv = kr[i];
            ax += qv[i].x * kv.x; ay += qv[i].y * kv.y;
            az += qv[i].z * kv.z; aw += qv[i].w * kv.w;
        }
        float p = (ax + ay) + (az + aw);
        p += __shfl_xor_sync(0xFFFFFFFFu, p, 16);
        s[g] = p * ms[h * HEADS + g];
    }

    float m = s[0];
    #pragma unroll
    for (int g = 1; g < 16; g++) m = fmaxf(m, s[g]);
    float denom = 0.f;
    #pragma unroll
    for (int g = 0; g < 16; g++) { s[g] = expf(s[g] - m); denom += s[g]; }
    const float inv = 1.f / denom;

    float4 o[8];
    #pragma unroll
    for (int i = 0; i < 8; i++) o[i] = make_float4(0.f, 0.f, 0.f, 0.f);
    #pragma unroll
    for (int g = 0; g < 16; g++) {
        const float p = s[g] * inv;
        const float4* vr = (const float4*)(vs + (t * HEADS + g) * DH + half * 32);
        #pragma unroll
        for (int i = 0; i < 8; i++) {
            float4 vv = vr[i];
            o[i].x += p * vv.x; o[i].y += p * vv.y;
            o[i].z += p * vv.z; o[i].w += p * vv.w;
        }
    }

    float4* op = (float4*)(out + (tok0 + t) * EDIM + h * DH + half * 32);
    #pragma unroll
    for (int i = 0; i < 8; i++) op[i] = o[i];
}

// ---------------------------------------------------------------------------
// Launch. Inputs: x, sparsity_pattern, Wq, bq, Wk, bk, Wv, bv
// ---------------------------------------------------------------------------
extern "C" void kernel_launch(void* const* d_in, const int* in_sizes, int n_in,
                              void* d_out, int out_size)
{
    (void)in_sizes; (void)n_in; (void)out_size;
    const float* x  = (const float*)d_in[0];
    const float* sp = (const float*)d_in[1];
    const float* Wq = (const float*)d_in[2];
    const float* bq = (const float*)d_in[3];
    const float* Wk = (const float*)d_in[4];
    const float* bk = (const float*)d_in[5];
    const float* Wv = (const float*)d_in[6];
    const float* bv = (const float*)d_in[7];
    float* out = (float*)d_out;

    pack_x<<<4096, 256>>>((const float4*)x);
    pack_w<<<1536, 256>>>((const float4*)Wq, (const float4*)Wk, (const float4*)Wv);
    pack_bias<<<12, 256>>>(bq, bk, bv);

    cudaFuncSetAttribute(qkv_mma_gemm,
                         cudaFuncAttributeMaxDynamicSharedMemorySize, SMEM_GEMM);
    dim3 grid(NTOT / GBN, M_TOK / GBM);    // (24, 128), x-major => A-tile reuse
    qkv_mma_gemm<<<grid, 256, SMEM_GEMM>>>();

    attn_kernel<<<M_TOK / 4, 128>>>(sp, out);
}